// round 13
// baseline (speedup 1.0000x reference)
#include <cuda_runtime.h>
#include <cuda_fp16.h>

// BlockDiagAttention: B=4,H=16,N=4128,D=64. fp32 in/out.
// R13: 64-thread CTA, 2 warps/tile, 32 Q-rows per warp -> K/V ldmatrix
// fragments read 2x per tile (was 4x). Pure fp16 Q,K,V,P (fp32 accum);
// deferred softmax normalization. 8 CTAs/SM, 18.4KB smem.
#define NSEQ  4128
#define TILES 65
#define QSTR  36   // u32 per smem row (144 B)

__device__ __forceinline__ void mma16816h(float c[4], const unsigned a[4],
                                          const unsigned b[2]) {
    asm volatile(
        "mma.sync.aligned.m16n8k16.row.col.f32.f16.f16.f32 "
        "{%0,%1,%2,%3}, {%4,%5,%6,%7}, {%8,%9}, {%0,%1,%2,%3};"
        : "+f"(c[0]), "+f"(c[1]), "+f"(c[2]), "+f"(c[3])
        : "r"(a[0]), "r"(a[1]), "r"(a[2]), "r"(a[3]), "r"(b[0]), "r"(b[1]));
}

__device__ __forceinline__ void ldsm_x4(unsigned r[4], unsigned addr) {
    asm volatile("ldmatrix.sync.aligned.m8n8.x4.shared.b16 {%0,%1,%2,%3}, [%4];"
                 : "=r"(r[0]), "=r"(r[1]), "=r"(r[2]), "=r"(r[3]) : "r"(addr));
}

__device__ __forceinline__ void ldsm_x4_t(unsigned r[4], unsigned addr) {
    asm volatile("ldmatrix.sync.aligned.m8n8.x4.trans.shared.b16 {%0,%1,%2,%3}, [%4];"
                 : "=r"(r[0]), "=r"(r[1]), "=r"(r[2]), "=r"(r[3]) : "r"(addr));
}

__device__ __forceinline__ unsigned pack2h(float x0, float x1) {
    __half2 hh = __floats2half2_rn(x0, x1);
    return *(unsigned*)&hh;
}

extern __shared__ unsigned smem_u32[];

__global__ __launch_bounds__(64, 8)
void bd_attn_kernel(const float* __restrict__ q, const float* __restrict__ k,
                    const float* __restrict__ v, float* __restrict__ out)
{
    unsigned* sQ = smem_u32;               // Q fp16; later V fp16 (row-major)
    unsigned* sK = smem_u32 + 64 * QSTR;   // K fp16

    const int tid  = threadIdx.x;
    const int bh   = blockIdx.x / TILES;
    const int t_   = blockIdx.x % TILES;
    const int row0 = t_ * 64;
    const int nrows = min(64, NSEQ - row0);   // 64 or 32

    const size_t base = ((size_t)bh * NSEQ + row0) * 64;
    const float* qb = q + base;
    const float* kb = k + base;
    const float* vb = v + base;

    // ---- L2 prefetch of V (consumed after GEMM1)
    {
        const char* vp = (const char*)vb;
        int lines = (nrows * 64 * 4) >> 7;
        for (int l = tid; l < lines; l += 64)
            asm volatile("prefetch.global.L2 [%0];" :: "l"(vp + (size_t)l * 128));
    }

    // ---- Load Q,K -> smem fp16 (row-major, uint4 stores)
#pragma unroll
    for (int p = 0; p < 8; ++p) {
        int i  = tid + 64 * p;
        int r  = i >> 3;
        int c8 = (i & 7) << 3;
        float4 f0 = make_float4(0.f,0.f,0.f,0.f), f1 = f0, g0 = f0, g1 = f0;
        if (r < nrows) {
            f0 = *(const float4*)(qb + r * 64 + c8);
            f1 = *(const float4*)(qb + r * 64 + c8 + 4);
            g0 = *(const float4*)(kb + r * 64 + c8);
            g1 = *(const float4*)(kb + r * 64 + c8 + 4);
        }
        *(uint4*)&sQ[r * QSTR + (c8 >> 1)] =
            make_uint4(pack2h(f0.x, f0.y), pack2h(f0.z, f0.w),
                       pack2h(f1.x, f1.y), pack2h(f1.z, f1.w));
        *(uint4*)&sK[r * QSTR + (c8 >> 1)] =
            make_uint4(pack2h(g0.x, g0.y), pack2h(g0.z, g0.w),
                       pack2h(g1.x, g1.y), pack2h(g1.z, g1.w));
    }
    __syncthreads();

    const int lane = tid & 31;
    const int w    = tid >> 5;      // warp 0: rows 0..31, warp 1: rows 32..63
    const int g    = lane >> 2;
    const int t    = lane & 3;
    const int i8   = lane >> 3;

    const unsigned sQ_b = (unsigned)__cvta_generic_to_shared(sQ);
    const unsigned sK_b = (unsigned)__cvta_generic_to_shared(sK);

    // A frags: rowset s covers rows 32w+16s .. +15
    const int aRow0 = 32 * w + (i8 & 1) * 8 + (lane & 7);
    const unsigned aOff0 = aRow0 * 144 + (i8 >> 1) * 16;
    const unsigned aOff1 = aOff0 + 16 * 144;
    const unsigned bOff = ((i8 >> 1) * 8 + (lane & 7)) * 144 + (i8 & 1) * 16;
    const unsigned cOff = ((i8 & 1) * 8 + (lane & 7)) * 144 + (i8 >> 1) * 16;

    // ---- GEMM1: S = Q K^T (pure fp16, fp32 accum). acc[rowset][nchunk][4]
    float acc[2][8][4];
#pragma unroll
    for (int s = 0; s < 2; ++s)
#pragma unroll
        for (int ch = 0; ch < 8; ++ch)
#pragma unroll
            for (int j = 0; j < 4; ++j) acc[s][ch][j] = 0.f;

#pragma unroll
    for (int kk = 0; kk < 4; ++kk) {
        unsigned a0[4], a1[4];
        ldsm_x4(a0, sQ_b + aOff0 + kk * 32);
        ldsm_x4(a1, sQ_b + aOff1 + kk * 32);
#pragma unroll
        for (int chp = 0; chp < 4; ++chp) {
            unsigned bb[4];
            ldsm_x4(bb, sK_b + bOff + chp * 2304 + kk * 32);
            mma16816h(acc[0][2*chp],   a0, &bb[0]);
            mma16816h(acc[0][2*chp+1], a0, &bb[2]);
            mma16816h(acc[1][2*chp],   a1, &bb[0]);
            mma16816h(acc[1][2*chp+1], a1, &bb[2]);
        }
    }

    // ---- softmax per rowset (unnormalized; normalize at epilogue)
    float sum0[2], sum1[2];
#pragma unroll
    for (int s = 0; s < 2; ++s) {
        float mx0 = -1e30f, mx1 = -1e30f;
#pragma unroll
        for (int ch = 0; ch < 8; ++ch) {
#pragma unroll
            for (int j = 0; j < 4; ++j) {
                int col = 8 * ch + 2 * t + (j & 1);
                acc[s][ch][j] = (col < nrows) ? acc[s][ch][j] * 0.125f : -1e30f;
            }
            mx0 = fmaxf(mx0, fmaxf(acc[s][ch][0], acc[s][ch][1]));
            mx1 = fmaxf(mx1, fmaxf(acc[s][ch][2], acc[s][ch][3]));
        }
        mx0 = fmaxf(mx0, __shfl_xor_sync(0xffffffffu, mx0, 1));
        mx0 = fmaxf(mx0, __shfl_xor_sync(0xffffffffu, mx0, 2));
        mx1 = fmaxf(mx1, __shfl_xor_sync(0xffffffffu, mx1, 1));
        mx1 = fmaxf(mx1, __shfl_xor_sync(0xffffffffu, mx1, 2));
        float s0 = 0.f, s1 = 0.f;
#pragma unroll
        for (int ch = 0; ch < 8; ++ch) {
            acc[s][ch][0] = __expf(acc[s][ch][0] - mx0);
            acc[s][ch][1] = __expf(acc[s][ch][1] - mx0);
            acc[s][ch][2] = __expf(acc[s][ch][2] - mx1);
            acc[s][ch][3] = __expf(acc[s][ch][3] - mx1);
            s0 += acc[s][ch][0] + acc[s][ch][1];
            s1 += acc[s][ch][2] + acc[s][ch][3];
        }
        s0 += __shfl_xor_sync(0xffffffffu, s0, 1);
        s0 += __shfl_xor_sync(0xffffffffu, s0, 2);
        s1 += __shfl_xor_sync(0xffffffffu, s1, 1);
        s1 += __shfl_xor_sync(0xffffffffu, s1, 2);
        sum0[s] = s0;
        sum1[s] = s1;
    }

    // ---- E fragments (pure fp16; E <= 1). pH[rowset][kk][4]
    unsigned pH[2][4][4];
#pragma unroll
    for (int s = 0; s < 2; ++s)
#pragma unroll
        for (int kk = 0; kk < 4; ++kk) {
            pH[s][kk][0] = pack2h(acc[s][2*kk][0],   acc[s][2*kk][1]);
            pH[s][kk][1] = pack2h(acc[s][2*kk][2],   acc[s][2*kk][3]);
            pH[s][kk][2] = pack2h(acc[s][2*kk+1][0], acc[s][2*kk+1][1]);
            pH[s][kk][3] = pack2h(acc[s][2*kk+1][2], acc[s][2*kk+1][3]);
        }

    __syncthreads();   // GEMM1 smem reads done; sQ becomes V (fp16)

    // ---- Load V -> smem fp16, ROW-MAJOR (batched LDGs, 2 groups of 4)
#pragma unroll
    for (int grp = 0; grp < 2; ++grp) {
        float4 va[4][2];
#pragma unroll
        for (int p = 0; p < 4; ++p) {
            int i  = tid + 64 * (grp * 4 + p);
            int r  = i >> 3;
            int c8 = (i & 7) << 3;
            va[p][0] = make_float4(0.f,0.f,0.f,0.f);
            va[p][1] = va[p][0];
            if (r < nrows) {
                va[p][0] = *(const float4*)(vb + r * 64 + c8);
                va[p][1] = *(const float4*)(vb + r * 64 + c8 + 4);
            }
        }
#pragma unroll
        for (int p = 0; p < 4; ++p) {
            int i  = tid + 64 * (grp * 4 + p);
            int r  = i >> 3;
            int c8 = (i & 7) << 3;
            *(uint4*)&sQ[r * QSTR + (c8 >> 1)] =
                make_uint4(pack2h(va[p][0].x, va[p][0].y),
                           pack2h(va[p][0].z, va[p][0].w),
                           pack2h(va[p][1].x, va[p][1].y),
                           pack2h(va[p][1].z, va[p][1].w));
        }
    }
    __syncthreads();

    // ---- GEMM2: O = E V (pure fp16)
#pragma unroll
    for (int s = 0; s < 2; ++s)
#pragma unroll
        for (int ch = 0; ch < 8; ++ch)
#pragma unroll
            for (int j = 0; j < 4; ++j) acc[s][ch][j] = 0.f;

#pragma unroll
    for (int kk = 0; kk < 4; ++kk) {
#pragma unroll
        for (int chp = 0; chp < 4; ++chp) {
            unsigned vv[4];
            ldsm_x4_t(vv, sQ_b + cOff + kk * 2304 + chp * 32);
            mma16816h(acc[0][2*chp],   pH[0][kk], &vv[0]);
            mma16816h(acc[0][2*chp+1], pH[0][kk], &vv[2]);
            mma16816h(acc[1][2*chp],   pH[1][kk], &vv[0]);
            mma16816h(acc[1][2*chp+1], pH[1][kk], &vv[2]);
        }
    }

    // ---- epilogue: normalize and write
    float* ob = out + base;
#pragma unroll
    for (int s = 0; s < 2; ++s) {
        const float inv0 = __frcp_rn(sum0[s]);
        const float inv1 = __frcp_rn(sum1[s]);
        const int r0 = 32 * w + 16 * s + g;
        const int r1 = r0 + 8;
#pragma unroll
        for (int ch = 0; ch < 8; ++ch) {
            int col = 8 * ch + 2 * t;
            if (r0 < nrows)
                *(float2*)(ob + r0 * 64 + col) =
                    make_float2(acc[s][ch][0] * inv0, acc[s][ch][1] * inv0);
            if (r1 < nrows)
                *(float2*)(ob + r1 * 64 + col) =
                    make_float2(acc[s][ch][2] * inv1, acc[s][ch][3] * inv1);
        }
    }
}

extern "C" void kernel_launch(void* const* d_in, const int* in_sizes, int n_in,
                              void* d_out, int out_size) {
    const float* q = (const float*)d_in[0];
    const float* k = (const float*)d_in[1];
    const float* v = (const float*)d_in[2];
    float* out = (float*)d_out;

    const int bh = in_sizes[0] / (NSEQ * 64);                      // 64
    const int smem_bytes = 2 * 64 * QSTR * (int)sizeof(unsigned);  // 18432

    cudaFuncSetAttribute(bd_attn_kernel,
                         cudaFuncAttributeMaxDynamicSharedMemorySize, smem_bytes);
    bd_attn_kernel<<<bh * TILES, 64, smem_bytes>>>(q, k, v, out);
}

// round 14
// speedup vs baseline: 1.1255x; 1.1255x over previous
#include <cuda_runtime.h>
#include <cuda_fp16.h>

// BlockDiagAttention: B=4,H=16,N=4128,D=64. fp32 in/out.
// R14 = R12 (128 thr, 4 warps, pure fp16 QKV, compensated P, 5 CTAs/SM)
// + dedicated V buffer: single front load phase, ONE barrier, no mid bubble.
// smem 27.6KB.
#define NSEQ  4128
#define TILES 65
#define QSTR  36   // u32 per smem row (144 B)

__device__ __forceinline__ void mma16816h(float c[4], const unsigned a[4],
                                          const unsigned b[2]) {
    asm volatile(
        "mma.sync.aligned.m16n8k16.row.col.f32.f16.f16.f32 "
        "{%0,%1,%2,%3}, {%4,%5,%6,%7}, {%8,%9}, {%0,%1,%2,%3};"
        : "+f"(c[0]), "+f"(c[1]), "+f"(c[2]), "+f"(c[3])
        : "r"(a[0]), "r"(a[1]), "r"(a[2]), "r"(a[3]), "r"(b[0]), "r"(b[1]));
}

__device__ __forceinline__ void ldsm_x4(unsigned r[4], unsigned addr) {
    asm volatile("ldmatrix.sync.aligned.m8n8.x4.shared.b16 {%0,%1,%2,%3}, [%4];"
                 : "=r"(r[0]), "=r"(r[1]), "=r"(r[2]), "=r"(r[3]) : "r"(addr));
}

__device__ __forceinline__ void ldsm_x4_t(unsigned r[4], unsigned addr) {
    asm volatile("ldmatrix.sync.aligned.m8n8.x4.trans.shared.b16 {%0,%1,%2,%3}, [%4];"
                 : "=r"(r[0]), "=r"(r[1]), "=r"(r[2]), "=r"(r[3]) : "r"(addr));
}

// fp16 split: hi = f16(x), lo = f16(x - hi).
__device__ __forceinline__ void split2h(float x0, float x1, unsigned& h, unsigned& l) {
    __half2 hh = __floats2half2_rn(x0, x1);
    float r0 = x0 - __half2float(__low2half(hh));
    float r1 = x1 - __half2float(__high2half(hh));
    __half2 ll = __floats2half2_rn(r0, r1);
    h = *(unsigned*)&hh;
    l = *(unsigned*)&ll;
}

__device__ __forceinline__ unsigned pack2h(float x0, float x1) {
    __half2 hh = __floats2half2_rn(x0, x1);
    return *(unsigned*)&hh;
}

extern __shared__ unsigned smem_u32[];

__global__ __launch_bounds__(128, 5)
void bd_attn_kernel(const float* __restrict__ q, const float* __restrict__ k,
                    const float* __restrict__ v, float* __restrict__ out)
{
    unsigned* sQ = smem_u32;               // Q fp16
    unsigned* sK = smem_u32 + 64 * QSTR;   // K fp16
    unsigned* sV = smem_u32 + 2 * 64 * QSTR;   // V fp16

    const int tid  = threadIdx.x;
    const int bh   = blockIdx.x / TILES;
    const int t_   = blockIdx.x % TILES;
    const int row0 = t_ * 64;
    const int nrows = min(64, NSEQ - row0);   // 64 or 32

    const size_t base = ((size_t)bh * NSEQ + row0) * 64;
    const float* qb = q + base;
    const float* kb = k + base;
    const float* vb = v + base;

    // ---- Single front load phase: Q,K,V -> fp16 smem (row-major, uint4 STS)
#pragma unroll
    for (int p = 0; p < 4; ++p) {
        int i  = tid + 128 * p;
        int r  = i >> 3;
        int c8 = (i & 7) << 3;
        float4 f0 = make_float4(0.f,0.f,0.f,0.f);
        float4 f1 = f0, g0 = f0, g1 = f0, v0 = f0, v1 = f0;
        if (r < nrows) {
            f0 = *(const float4*)(qb + r * 64 + c8);
            f1 = *(const float4*)(qb + r * 64 + c8 + 4);
            g0 = *(const float4*)(kb + r * 64 + c8);
            g1 = *(const float4*)(kb + r * 64 + c8 + 4);
            v0 = *(const float4*)(vb + r * 64 + c8);
            v1 = *(const float4*)(vb + r * 64 + c8 + 4);
        }
        *(uint4*)&sQ[r * QSTR + (c8 >> 1)] =
            make_uint4(pack2h(f0.x, f0.y), pack2h(f0.z, f0.w),
                       pack2h(f1.x, f1.y), pack2h(f1.z, f1.w));
        *(uint4*)&sK[r * QSTR + (c8 >> 1)] =
            make_uint4(pack2h(g0.x, g0.y), pack2h(g0.z, g0.w),
                       pack2h(g1.x, g1.y), pack2h(g1.z, g1.w));
        *(uint4*)&sV[r * QSTR + (c8 >> 1)] =
            make_uint4(pack2h(v0.x, v0.y), pack2h(v0.z, v0.w),
                       pack2h(v1.x, v1.y), pack2h(v1.z, v1.w));
    }
    __syncthreads();   // the ONLY barrier

    const int lane = tid & 31;
    const int w    = tid >> 5;
    const int g    = lane >> 2;
    const int t    = lane & 3;
    const int i8   = lane >> 3;

    const unsigned sQ_b = (unsigned)__cvta_generic_to_shared(sQ);
    const unsigned sK_b = (unsigned)__cvta_generic_to_shared(sK);
    const unsigned sV_b = (unsigned)__cvta_generic_to_shared(sV);

    const int aRow = 16 * w + (i8 & 1) * 8 + (lane & 7);
    const unsigned aOff = aRow * 144 + (i8 >> 1) * 16;
    const unsigned bOff = ((i8 >> 1) * 8 + (lane & 7)) * 144 + (i8 & 1) * 16;
    const unsigned cOff = ((i8 & 1) * 8 + (lane & 7)) * 144 + (i8 >> 1) * 16;

    // ---- GEMM1: S = Q K^T  (pure fp16, fp32 accum), software-pipelined
    float acc[8][4];
#pragma unroll
    for (int ch = 0; ch < 8; ++ch)
#pragma unroll
        for (int j = 0; j < 4; ++j) acc[ch][j] = 0.f;

    {
        unsigned aH[2][4], bH[2][4];
        ldsm_x4(aH[0], sQ_b + aOff);
        ldsm_x4(bH[0], sK_b + bOff);
#pragma unroll
        for (int it = 0; it < 16; ++it) {
            const int kk  = it >> 2;
            const int chp = it & 3;
            const int cb  = it & 1;
            if (it < 15) {
                const int it2  = it + 1;
                const int kk2  = it2 >> 2;
                const int chp2 = it2 & 3;
                ldsm_x4(bH[it2 & 1], sK_b + bOff + chp2 * 2304 + kk2 * 32);
                if (chp == 3)
                    ldsm_x4(aH[kk2 & 1], sQ_b + aOff + kk2 * 32);
            }
            const int ab = kk & 1;
            mma16816h(acc[2*chp],   aH[ab], &bH[cb][0]);
            mma16816h(acc[2*chp+1], aH[ab], &bH[cb][2]);
        }
    }

    // ---- softmax (unnormalized; normalize at epilogue)
    float mx0 = -1e30f, mx1 = -1e30f;
#pragma unroll
    for (int ch = 0; ch < 8; ++ch) {
#pragma unroll
        for (int j = 0; j < 4; ++j) {
            int col = 8 * ch + 2 * t + (j & 1);
            acc[ch][j] = (col < nrows) ? acc[ch][j] * 0.125f : -1e30f;
        }
        mx0 = fmaxf(mx0, fmaxf(acc[ch][0], acc[ch][1]));
        mx1 = fmaxf(mx1, fmaxf(acc[ch][2], acc[ch][3]));
    }
    mx0 = fmaxf(mx0, __shfl_xor_sync(0xffffffffu, mx0, 1));
    mx0 = fmaxf(mx0, __shfl_xor_sync(0xffffffffu, mx0, 2));
    mx1 = fmaxf(mx1, __shfl_xor_sync(0xffffffffu, mx1, 1));
    mx1 = fmaxf(mx1, __shfl_xor_sync(0xffffffffu, mx1, 2));

    float sum0 = 0.f, sum1 = 0.f;
#pragma unroll
    for (int ch = 0; ch < 8; ++ch) {
        acc[ch][0] = __expf(acc[ch][0] - mx0);
        acc[ch][1] = __expf(acc[ch][1] - mx0);
        acc[ch][2] = __expf(acc[ch][2] - mx1);
        acc[ch][3] = __expf(acc[ch][3] - mx1);
        sum0 += acc[ch][0] + acc[ch][1];
        sum1 += acc[ch][2] + acc[ch][3];
    }
    sum0 += __shfl_xor_sync(0xffffffffu, sum0, 1);
    sum0 += __shfl_xor_sync(0xffffffffu, sum0, 2);
    sum1 += __shfl_xor_sync(0xffffffffu, sum1, 1);
    sum1 += __shfl_xor_sync(0xffffffffu, sum1, 2);

    // ---- eager E fragments: fp16 hi + lo (compensated; E <= 1)
    unsigned pH[4][4], pL[4][4];
#pragma unroll
    for (int kk = 0; kk < 4; ++kk) {
        split2h(acc[2*kk][0],   acc[2*kk][1],   pH[kk][0], pL[kk][0]);
        split2h(acc[2*kk][2],   acc[2*kk][3],   pH[kk][1], pL[kk][1]);
        split2h(acc[2*kk+1][0], acc[2*kk+1][1], pH[kk][2], pL[kk][2]);
        split2h(acc[2*kk+1][2], acc[2*kk+1][3], pH[kk][3], pL[kk][3]);
    }

    // ---- GEMM2: O = E V  (fp16: pH*V + pL*V), V double-buffered, no barrier
#pragma unroll
    for (int ch = 0; ch < 8; ++ch)
#pragma unroll
        for (int j = 0; j < 4; ++j) acc[ch][j] = 0.f;

    {
        unsigned vH[2][4];
        ldsm_x4_t(vH[0], sV_b + cOff);
#pragma unroll
        for (int it = 0; it < 16; ++it) {
            const int kk  = it >> 2;
            const int chp = it & 3;
            const int cb  = it & 1;
            if (it < 15) {
                const int it2  = it + 1;
                const int kk2  = it2 >> 2;
                const int chp2 = it2 & 3;
                ldsm_x4_t(vH[it2 & 1], sV_b + cOff + kk2 * 2304 + chp2 * 32);
            }
            mma16816h(acc[2*chp],   pH[kk], &vH[cb][0]);
            mma16816h(acc[2*chp],   pL[kk], &vH[cb][0]);
            mma16816h(acc[2*chp+1], pH[kk], &vH[cb][2]);
            mma16816h(acc[2*chp+1], pL[kk], &vH[cb][2]);
        }
    }

    // ---- epilogue: normalize and write
    const float inv0 = __frcp_rn(sum0);
    const float inv1 = __frcp_rn(sum1);
    float* ob = out + base;
    const int r0 = 16 * w + g;
    const int r1 = r0 + 8;
#pragma unroll
    for (int ch = 0; ch < 8; ++ch) {
        int col = 8 * ch + 2 * t;
        if (r0 < nrows)
            *(float2*)(ob + r0 * 64 + col) =
                make_float2(acc[ch][0] * inv0, acc[ch][1] * inv0);
        if (r1 < nrows)
            *(float2*)(ob + r1 * 64 + col) =
                make_float2(acc[ch][2] * inv1, acc[ch][3] * inv1);
    }
}

extern "C" void kernel_launch(void* const* d_in, const int* in_sizes, int n_in,
                              void* d_out, int out_size) {
    const float* q = (const float*)d_in[0];
    const float* k = (const float*)d_in[1];
    const float* v = (const float*)d_in[2];
    float* out = (float*)d_out;

    const int bh = in_sizes[0] / (NSEQ * 64);                      // 64
    const int smem_bytes = 3 * 64 * QSTR * (int)sizeof(unsigned);  // 27648

    cudaFuncSetAttribute(bd_attn_kernel,
                         cudaFuncAttributeMaxDynamicSharedMemorySize, smem_bytes);
    bd_attn_kernel<<<bh * TILES, 128, smem_bytes>>>(q, k, v, out);
}

// round 15
// speedup vs baseline: 1.1448x; 1.0172x over previous
#include <cuda_runtime.h>
#include <cuda_fp16.h>

// BlockDiagAttention: B=4,H=16,N=4128,D=64. fp32 in/out.
// R15 = R12 base (128 thr, two-phase V-reuse, 18.4KB smem, pipelined GEMMs,
// pure fp16 Q,K,V, deferred norm) + pure fp16 P (no lo term; GEMM2 MMAs
// halved) + 6 CTAs/SM (regs ~80 after dropping pL).
#define NSEQ  4128
#define TILES 65
#define QSTR  36   // u32 per smem row (144 B)

__device__ __forceinline__ void mma16816h(float c[4], const unsigned a[4],
                                          const unsigned b[2]) {
    asm volatile(
        "mma.sync.aligned.m16n8k16.row.col.f32.f16.f16.f32 "
        "{%0,%1,%2,%3}, {%4,%5,%6,%7}, {%8,%9}, {%0,%1,%2,%3};"
        : "+f"(c[0]), "+f"(c[1]), "+f"(c[2]), "+f"(c[3])
        : "r"(a[0]), "r"(a[1]), "r"(a[2]), "r"(a[3]), "r"(b[0]), "r"(b[1]));
}

__device__ __forceinline__ void ldsm_x4(unsigned r[4], unsigned addr) {
    asm volatile("ldmatrix.sync.aligned.m8n8.x4.shared.b16 {%0,%1,%2,%3}, [%4];"
                 : "=r"(r[0]), "=r"(r[1]), "=r"(r[2]), "=r"(r[3]) : "r"(addr));
}

__device__ __forceinline__ void ldsm_x4_t(unsigned r[4], unsigned addr) {
    asm volatile("ldmatrix.sync.aligned.m8n8.x4.trans.shared.b16 {%0,%1,%2,%3}, [%4];"
                 : "=r"(r[0]), "=r"(r[1]), "=r"(r[2]), "=r"(r[3]) : "r"(addr));
}

__device__ __forceinline__ unsigned pack2h(float x0, float x1) {
    __half2 hh = __floats2half2_rn(x0, x1);
    return *(unsigned*)&hh;
}

extern __shared__ unsigned smem_u32[];

__global__ __launch_bounds__(128, 6)
void bd_attn_kernel(const float* __restrict__ q, const float* __restrict__ k,
                    const float* __restrict__ v, float* __restrict__ out)
{
    unsigned* sQ = smem_u32;               // Q fp16; later V fp16 (row-major)
    unsigned* sK = smem_u32 + 64 * QSTR;   // K fp16

    const int tid  = threadIdx.x;
    const int bh   = blockIdx.x / TILES;
    const int t_   = blockIdx.x % TILES;
    const int row0 = t_ * 64;
    const int nrows = min(64, NSEQ - row0);   // 64 or 32

    const size_t base = ((size_t)bh * NSEQ + row0) * 64;
    const float* qb = q + base;
    const float* kb = k + base;
    const float* vb = v + base;

    // ---- L2 prefetch of V (consumed after GEMM1)
    {
        const char* vp = (const char*)vb;
        int lines = (nrows * 64 * 4) >> 7;
        for (int l = tid; l < lines; l += 128)
            asm volatile("prefetch.global.L2 [%0];" :: "l"(vp + (size_t)l * 128));
    }

    // ---- Load Q,K -> smem fp16 (row-major, uint4 stores)
#pragma unroll
    for (int p = 0; p < 4; ++p) {
        int i  = tid + 128 * p;
        int r  = i >> 3;
        int c8 = (i & 7) << 3;
        float4 f0 = make_float4(0.f,0.f,0.f,0.f), f1 = f0, g0 = f0, g1 = f0;
        if (r < nrows) {
            f0 = *(const float4*)(qb + r * 64 + c8);
            f1 = *(const float4*)(qb + r * 64 + c8 + 4);
            g0 = *(const float4*)(kb + r * 64 + c8);
            g1 = *(const float4*)(kb + r * 64 + c8 + 4);
        }
        *(uint4*)&sQ[r * QSTR + (c8 >> 1)] =
            make_uint4(pack2h(f0.x, f0.y), pack2h(f0.z, f0.w),
                       pack2h(f1.x, f1.y), pack2h(f1.z, f1.w));
        *(uint4*)&sK[r * QSTR + (c8 >> 1)] =
            make_uint4(pack2h(g0.x, g0.y), pack2h(g0.z, g0.w),
                       pack2h(g1.x, g1.y), pack2h(g1.z, g1.w));
    }
    __syncthreads();

    const int lane = tid & 31;
    const int w    = tid >> 5;
    const int g    = lane >> 2;
    const int t    = lane & 3;
    const int i8   = lane >> 3;

    const unsigned sQ_b = (unsigned)__cvta_generic_to_shared(sQ);
    const unsigned sK_b = (unsigned)__cvta_generic_to_shared(sK);

    const int aRow = 16 * w + (i8 & 1) * 8 + (lane & 7);
    const unsigned aOff = aRow * 144 + (i8 >> 1) * 16;
    const unsigned bOff = ((i8 >> 1) * 8 + (lane & 7)) * 144 + (i8 & 1) * 16;
    const unsigned cOff = ((i8 & 1) * 8 + (lane & 7)) * 144 + (i8 >> 1) * 16;

    // ---- GEMM1: S = Q K^T  (pure fp16, fp32 accum), software-pipelined
    float acc[8][4];
#pragma unroll
    for (int ch = 0; ch < 8; ++ch)
#pragma unroll
        for (int j = 0; j < 4; ++j) acc[ch][j] = 0.f;

    {
        unsigned aH[2][4], bH[2][4];
        ldsm_x4(aH[0], sQ_b + aOff);
        ldsm_x4(bH[0], sK_b + bOff);
#pragma unroll
        for (int it = 0; it < 16; ++it) {
            const int kk  = it >> 2;
            const int chp = it & 3;
            const int cb  = it & 1;
            if (it < 15) {
                const int it2  = it + 1;
                const int kk2  = it2 >> 2;
                const int chp2 = it2 & 3;
                ldsm_x4(bH[it2 & 1], sK_b + bOff + chp2 * 2304 + kk2 * 32);
                if (chp == 3)
                    ldsm_x4(aH[kk2 & 1], sQ_b + aOff + kk2 * 32);
            }
            const int ab = kk & 1;
            mma16816h(acc[2*chp],   aH[ab], &bH[cb][0]);
            mma16816h(acc[2*chp+1], aH[ab], &bH[cb][2]);
        }
    }

    // ---- softmax (unnormalized; normalize at epilogue)
    float mx0 = -1e30f, mx1 = -1e30f;
#pragma unroll
    for (int ch = 0; ch < 8; ++ch) {
#pragma unroll
        for (int j = 0; j < 4; ++j) {
            int col = 8 * ch + 2 * t + (j & 1);
            acc[ch][j] = (col < nrows) ? acc[ch][j] * 0.125f : -1e30f;
        }
        mx0 = fmaxf(mx0, fmaxf(acc[ch][0], acc[ch][1]));
        mx1 = fmaxf(mx1, fmaxf(acc[ch][2], acc[ch][3]));
    }
    mx0 = fmaxf(mx0, __shfl_xor_sync(0xffffffffu, mx0, 1));
    mx0 = fmaxf(mx0, __shfl_xor_sync(0xffffffffu, mx0, 2));
    mx1 = fmaxf(mx1, __shfl_xor_sync(0xffffffffu, mx1, 1));
    mx1 = fmaxf(mx1, __shfl_xor_sync(0xffffffffu, mx1, 2));

    float sum0 = 0.f, sum1 = 0.f;
#pragma unroll
    for (int ch = 0; ch < 8; ++ch) {
        acc[ch][0] = __expf(acc[ch][0] - mx0);
        acc[ch][1] = __expf(acc[ch][1] - mx0);
        acc[ch][2] = __expf(acc[ch][2] - mx1);
        acc[ch][3] = __expf(acc[ch][3] - mx1);
        sum0 += acc[ch][0] + acc[ch][1];
        sum1 += acc[ch][2] + acc[ch][3];
    }
    sum0 += __shfl_xor_sync(0xffffffffu, sum0, 1);
    sum0 += __shfl_xor_sync(0xffffffffu, sum0, 2);
    sum1 += __shfl_xor_sync(0xffffffffu, sum1, 1);
    sum1 += __shfl_xor_sync(0xffffffffu, sum1, 2);

    // ---- E fragments: pure fp16 (E <= 1)
    unsigned pH[4][4];
#pragma unroll
    for (int kk = 0; kk < 4; ++kk) {
        pH[kk][0] = pack2h(acc[2*kk][0],   acc[2*kk][1]);
        pH[kk][1] = pack2h(acc[2*kk][2],   acc[2*kk][3]);
        pH[kk][2] = pack2h(acc[2*kk+1][0], acc[2*kk+1][1]);
        pH[kk][3] = pack2h(acc[2*kk+1][2], acc[2*kk+1][3]);
    }

    __syncthreads();   // GEMM1 smem reads done; sQ becomes V (fp16)

    // ---- Load V -> smem fp16, ROW-MAJOR (all LDGs first)
    {
        float4 va[4][2];
#pragma unroll
        for (int p = 0; p < 4; ++p) {
            int i  = tid + 128 * p;
            int r  = i >> 3;
            int c8 = (i & 7) << 3;
            va[p][0] = make_float4(0.f,0.f,0.f,0.f);
            va[p][1] = va[p][0];
            if (r < nrows) {
                va[p][0] = *(const float4*)(vb + r * 64 + c8);
                va[p][1] = *(const float4*)(vb + r * 64 + c8 + 4);
            }
        }
#pragma unroll
        for (int p = 0; p < 4; ++p) {
            int i  = tid + 128 * p;
            int r  = i >> 3;
            int c8 = (i & 7) << 3;
            *(uint4*)&sQ[r * QSTR + (c8 >> 1)] =
                make_uint4(pack2h(va[p][0].x, va[p][0].y),
                           pack2h(va[p][0].z, va[p][0].w),
                           pack2h(va[p][1].x, va[p][1].y),
                           pack2h(va[p][1].z, va[p][1].w));
        }
    }
    __syncthreads();

    // ---- GEMM2: O = E V  (pure fp16), V double-buffered
#pragma unroll
    for (int ch = 0; ch < 8; ++ch)
#pragma unroll
        for (int j = 0; j < 4; ++j) acc[ch][j] = 0.f;

    {
        unsigned vH[2][4];
        ldsm_x4_t(vH[0], sQ_b + cOff);
#pragma unroll
        for (int it = 0; it < 16; ++it) {
            const int kk  = it >> 2;
            const int chp = it & 3;
            const int cb  = it & 1;
            if (it < 15) {
                const int it2  = it + 1;
                const int kk2  = it2 >> 2;
                const int chp2 = it2 & 3;
                ldsm_x4_t(vH[it2 & 1], sQ_b + cOff + kk2 * 2304 + chp2 * 32);
            }
            mma16816h(acc[2*chp],   pH[kk], &vH[cb][0]);
            mma16816h(acc[2*chp+1], pH[kk], &vH[cb][2]);
        }
    }

    // ---- epilogue: normalize and write
    const float inv0 = __frcp_rn(sum0);
    const float inv1 = __frcp_rn(sum1);
    float* ob = out + base;
    const int r0 = 16 * w + g;
    const int r1 = r0 + 8;
#pragma unroll
    for (int ch = 0; ch < 8; ++ch) {
        int col = 8 * ch + 2 * t;
        if (r0 < nrows)
            *(float2*)(ob + r0 * 64 + col) =
                make_float2(acc[ch][0] * inv0, acc[ch][1] * inv0);
        if (r1 < nrows)
            *(float2*)(ob + r1 * 64 + col) =
                make_float2(acc[ch][2] * inv1, acc[ch][3] * inv1);
    }
}

extern "C" void kernel_launch(void* const* d_in, const int* in_sizes, int n_in,
                              void* d_out, int out_size) {
    const float* q = (const float*)d_in[0];
    const float* k = (const float*)d_in[1];
    const float* v = (const float*)d_in[2];
    float* out = (float*)d_out;

    const int bh = in_sizes[0] / (NSEQ * 64);                      // 64
    const int smem_bytes = 2 * 64 * QSTR * (int)sizeof(unsigned);  // 18432

    cudaFuncSetAttribute(bd_attn_kernel,
                         cudaFuncAttributeMaxDynamicSharedMemorySize, smem_bytes);
    bd_attn_kernel<<<bh * TILES, 128, smem_bytes>>>(q, k, v, out);
}

// round 16
// speedup vs baseline: 1.1586x; 1.0120x over previous
#include <cuda_runtime.h>
#include <cuda_fp16.h>

// BlockDiagAttention: B=4,H=16,N=4128,D=64. fp32 in/out.
// R16 = R15 numerics (pure fp16 Q,K,V,P; deferred norm; halved GEMM2 MMAs)
// at R12's proven occupancy: 5 CTAs/SM. 18.4KB smem, 128 thr.
#define NSEQ  4128
#define TILES 65
#define QSTR  36   // u32 per smem row (144 B)

__device__ __forceinline__ void mma16816h(float c[4], const unsigned a[4],
                                          const unsigned b[2]) {
    asm volatile(
        "mma.sync.aligned.m16n8k16.row.col.f32.f16.f16.f32 "
        "{%0,%1,%2,%3}, {%4,%5,%6,%7}, {%8,%9}, {%0,%1,%2,%3};"
        : "+f"(c[0]), "+f"(c[1]), "+f"(c[2]), "+f"(c[3])
        : "r"(a[0]), "r"(a[1]), "r"(a[2]), "r"(a[3]), "r"(b[0]), "r"(b[1]));
}

__device__ __forceinline__ void ldsm_x4(unsigned r[4], unsigned addr) {
    asm volatile("ldmatrix.sync.aligned.m8n8.x4.shared.b16 {%0,%1,%2,%3}, [%4];"
                 : "=r"(r[0]), "=r"(r[1]), "=r"(r[2]), "=r"(r[3]) : "r"(addr));
}

__device__ __forceinline__ void ldsm_x4_t(unsigned r[4], unsigned addr) {
    asm volatile("ldmatrix.sync.aligned.m8n8.x4.trans.shared.b16 {%0,%1,%2,%3}, [%4];"
                 : "=r"(r[0]), "=r"(r[1]), "=r"(r[2]), "=r"(r[3]) : "r"(addr));
}

__device__ __forceinline__ unsigned pack2h(float x0, float x1) {
    __half2 hh = __floats2half2_rn(x0, x1);
    return *(unsigned*)&hh;
}

extern __shared__ unsigned smem_u32[];

__global__ __launch_bounds__(128, 5)
void bd_attn_kernel(const float* __restrict__ q, const float* __restrict__ k,
                    const float* __restrict__ v, float* __restrict__ out)
{
    unsigned* sQ = smem_u32;               // Q fp16; later V fp16 (row-major)
    unsigned* sK = smem_u32 + 64 * QSTR;   // K fp16

    const int tid  = threadIdx.x;
    const int bh   = blockIdx.x / TILES;
    const int t_   = blockIdx.x % TILES;
    const int row0 = t_ * 64;
    const int nrows = min(64, NSEQ - row0);   // 64 or 32

    const size_t base = ((size_t)bh * NSEQ + row0) * 64;
    const float* qb = q + base;
    const float* kb = k + base;
    const float* vb = v + base;

    // ---- L2 prefetch of V (consumed after GEMM1)
    {
        const char* vp = (const char*)vb;
        int lines = (nrows * 64 * 4) >> 7;
        for (int l = tid; l < lines; l += 128)
            asm volatile("prefetch.global.L2 [%0];" :: "l"(vp + (size_t)l * 128));
    }

    // ---- Load Q,K -> smem fp16 (row-major, uint4 stores)
#pragma unroll
    for (int p = 0; p < 4; ++p) {
        int i  = tid + 128 * p;
        int r  = i >> 3;
        int c8 = (i & 7) << 3;
        float4 f0 = make_float4(0.f,0.f,0.f,0.f), f1 = f0, g0 = f0, g1 = f0;
        if (r < nrows) {
            f0 = *(const float4*)(qb + r * 64 + c8);
            f1 = *(const float4*)(qb + r * 64 + c8 + 4);
            g0 = *(const float4*)(kb + r * 64 + c8);
            g1 = *(const float4*)(kb + r * 64 + c8 + 4);
        }
        *(uint4*)&sQ[r * QSTR + (c8 >> 1)] =
            make_uint4(pack2h(f0.x, f0.y), pack2h(f0.z, f0.w),
                       pack2h(f1.x, f1.y), pack2h(f1.z, f1.w));
        *(uint4*)&sK[r * QSTR + (c8 >> 1)] =
            make_uint4(pack2h(g0.x, g0.y), pack2h(g0.z, g0.w),
                       pack2h(g1.x, g1.y), pack2h(g1.z, g1.w));
    }
    __syncthreads();

    const int lane = tid & 31;
    const int w    = tid >> 5;
    const int g    = lane >> 2;
    const int t    = lane & 3;
    const int i8   = lane >> 3;

    const unsigned sQ_b = (unsigned)__cvta_generic_to_shared(sQ);
    const unsigned sK_b = (unsigned)__cvta_generic_to_shared(sK);

    const int aRow = 16 * w + (i8 & 1) * 8 + (lane & 7);
    const unsigned aOff = aRow * 144 + (i8 >> 1) * 16;
    const unsigned bOff = ((i8 >> 1) * 8 + (lane & 7)) * 144 + (i8 & 1) * 16;
    const unsigned cOff = ((i8 & 1) * 8 + (lane & 7)) * 144 + (i8 >> 1) * 16;

    // ---- GEMM1: S = Q K^T  (pure fp16, fp32 accum), software-pipelined
    float acc[8][4];
#pragma unroll
    for (int ch = 0; ch < 8; ++ch)
#pragma unroll
        for (int j = 0; j < 4; ++j) acc[ch][j] = 0.f;

    {
        unsigned aH[2][4], bH[2][4];
        ldsm_x4(aH[0], sQ_b + aOff);
        ldsm_x4(bH[0], sK_b + bOff);
#pragma unroll
        for (int it = 0; it < 16; ++it) {
            const int kk  = it >> 2;
            const int chp = it & 3;
            const int cb  = it & 1;
            if (it < 15) {
                const int it2  = it + 1;
                const int kk2  = it2 >> 2;
                const int chp2 = it2 & 3;
                ldsm_x4(bH[it2 & 1], sK_b + bOff + chp2 * 2304 + kk2 * 32);
                if (chp == 3)
                    ldsm_x4(aH[kk2 & 1], sQ_b + aOff + kk2 * 32);
            }
            const int ab = kk & 1;
            mma16816h(acc[2*chp],   aH[ab], &bH[cb][0]);
            mma16816h(acc[2*chp+1], aH[ab], &bH[cb][2]);
        }
    }

    // ---- softmax (unnormalized; normalize at epilogue)
    float mx0 = -1e30f, mx1 = -1e30f;
#pragma unroll
    for (int ch = 0; ch < 8; ++ch) {
#pragma unroll
        for (int j = 0; j < 4; ++j) {
            int col = 8 * ch + 2 * t + (j & 1);
            acc[ch][j] = (col < nrows) ? acc[ch][j] * 0.125f : -1e30f;
        }
        mx0 = fmaxf(mx0, fmaxf(acc[ch][0], acc[ch][1]));
        mx1 = fmaxf(mx1, fmaxf(acc[ch][2], acc[ch][3]));
    }
    mx0 = fmaxf(mx0, __shfl_xor_sync(0xffffffffu, mx0, 1));
    mx0 = fmaxf(mx0, __shfl_xor_sync(0xffffffffu, mx0, 2));
    mx1 = fmaxf(mx1, __shfl_xor_sync(0xffffffffu, mx1, 1));
    mx1 = fmaxf(mx1, __shfl_xor_sync(0xffffffffu, mx1, 2));

    float sum0 = 0.f, sum1 = 0.f;
#pragma unroll
    for (int ch = 0; ch < 8; ++ch) {
        acc[ch][0] = __expf(acc[ch][0] - mx0);
        acc[ch][1] = __expf(acc[ch][1] - mx0);
        acc[ch][2] = __expf(acc[ch][2] - mx1);
        acc[ch][3] = __expf(acc[ch][3] - mx1);
        sum0 += acc[ch][0] + acc[ch][1];
        sum1 += acc[ch][2] + acc[ch][3];
    }
    sum0 += __shfl_xor_sync(0xffffffffu, sum0, 1);
    sum0 += __shfl_xor_sync(0xffffffffu, sum0, 2);
    sum1 += __shfl_xor_sync(0xffffffffu, sum1, 1);
    sum1 += __shfl_xor_sync(0xffffffffu, sum1, 2);

    // ---- E fragments: pure fp16 (E <= 1)
    unsigned pH[4][4];
#pragma unroll
    for (int kk = 0; kk < 4; ++kk) {
        pH[kk][0] = pack2h(acc[2*kk][0],   acc[2*kk][1]);
        pH[kk][1] = pack2h(acc[2*kk][2],   acc[2*kk][3]);
        pH[kk][2] = pack2h(acc[2*kk+1][0], acc[2*kk+1][1]);
        pH[kk][3] = pack2h(acc[2*kk+1][2], acc[2*kk+1][3]);
    }

    __syncthreads();   // GEMM1 smem reads done; sQ becomes V (fp16)

    // ---- Load V -> smem fp16, ROW-MAJOR (all LDGs first)
    {
        float4 va[4][2];
#pragma unroll
        for (int p = 0; p < 4; ++p) {
            int i  = tid + 128 * p;
            int r  = i >> 3;
            int c8 = (i & 7) << 3;
            va[p][0] = make_float4(0.f,0.f,0.f,0.f);
            va[p][1] = va[p][0];
            if (r < nrows) {
                va[p][0] = *(const float4*)(vb + r * 64 + c8);
                va[p][1] = *(const float4*)(vb + r * 64 + c8 + 4);
            }
        }
#pragma unroll
        for (int p = 0; p < 4; ++p) {
            int i  = tid + 128 * p;
            int r  = i >> 3;
            int c8 = (i & 7) << 3;
            *(uint4*)&sQ[r * QSTR + (c8 >> 1)] =
                make_uint4(pack2h(va[p][0].x, va[p][0].y),
                           pack2h(va[p][0].z, va[p][0].w),
                           pack2h(va[p][1].x, va[p][1].y),
                           pack2h(va[p][1].z, va[p][1].w));
        }
    }
    __syncthreads();

    // ---- GEMM2: O = E V  (pure fp16), V double-buffered
#pragma unroll
    for (int ch = 0; ch < 8; ++ch)
#pragma unroll
        for (int j = 0; j < 4; ++j) acc[ch][j] = 0.f;

    {
        unsigned vH[2][4];
        ldsm_x4_t(vH[0], sQ_b + cOff);
#pragma unroll
        for (int it = 0; it < 16; ++it) {
            const int kk  = it >> 2;
            const int chp = it & 3;
            const int cb  = it & 1;
            if (it < 15) {
                const int it2  = it + 1;
                const int kk2  = it2 >> 2;
                const int chp2 = it2 & 3;
                ldsm_x4_t(vH[it2 & 1], sQ_b + cOff + kk2 * 2304 + chp2 * 32);
            }
            mma16816h(acc[2*chp],   pH[kk], &vH[cb][0]);
            mma16816h(acc[2*chp+1], pH[kk], &vH[cb][2]);
        }
    }

    // ---- epilogue: normalize and write
    const float inv0 = __frcp_rn(sum0);
    const float inv1 = __frcp_rn(sum1);
    float* ob = out + base;
    const int r0 = 16 * w + g;
    const int r1 = r0 + 8;
#pragma unroll
    for (int ch = 0; ch < 8; ++ch) {
        int col = 8 * ch + 2 * t;
        if (r0 < nrows)
            *(float2*)(ob + r0 * 64 + col) =
                make_float2(acc[ch][0] * inv0, acc[ch][1] * inv0);
        if (r1 < nrows)
            *(float2*)(ob + r1 * 64 + col) =
                make_float2(acc[ch][2] * inv1, acc[ch][3] * inv1);
    }
}

extern "C" void kernel_launch(void* const* d_in, const int* in_sizes, int n_in,
                              void* d_out, int out_size) {
    const float* q = (const float*)d_in[0];
    const float* k = (const float*)d_in[1];
    const float* v = (const float*)d_in[2];
    float* out = (float*)d_out;

    const int bh = in_sizes[0] / (NSEQ * 64);                      // 64
    const int smem_bytes = 2 * 64 * QSTR * (int)sizeof(unsigned);  // 18432

    cudaFuncSetAttribute(bd_attn_kernel,
                         cudaFuncAttributeMaxDynamicSharedMemorySize, smem_bytes);
    bd_attn_kernel<<<bh * TILES, 128, smem_bytes>>>(q, k, v, out);
}